// round 15
// baseline (speedup 1.0000x reference)
#include <cuda_runtime.h>
#include <cuda_bf16.h>
#include <math.h>
#include <stdint.h>
#include <stddef.h>

// Problem constants (fixed by the reference setup_inputs)
#define BATCH  2
#define NTOK   4096
#define DMODEL 512
#define HEADS  8
#define HDIM   64
#define KNN    9
#define MROWS  (BATCH * NTOK)          // 8192
#define GRID   64
#define CELLS  (GRID * GRID)
#define CELLSZ 1.5625f                 // 100/64
#define INVCELL 0.64f                  // 64/100

// Scratch (static __device__ arrays: allocation-free, harness-legal)
__device__ __nv_bfloat16  g_qb[(size_t)MROWS * DMODEL];          // bf16 Q
__device__ __nv_bfloat16  g_kvb[(size_t)MROWS * 2 * DMODEL];     // bf16 K|V
__device__ __nv_bfloat16  g_attnb[(size_t)MROWS * DMODEL];       // bf16 GELU(attn)
__device__ __nv_bfloat16  g_wqb[(size_t)3 * DMODEL * DMODEL];    // bf16 w_qkv
__device__ __nv_bfloat16  g_wpb[(size_t)DMODEL * DMODEL];        // bf16 w_proj
__device__ int            g_nn[(size_t)MROWS * KNN];
__device__ int            g_cellstart[BATCH * (CELLS + 1)];
__device__ float2         g_scoord[BATCH * NTOK];
__device__ int            g_sidx[BATCH * NTOK];

// ===========================================================================
// PTX helpers (base sm_103 ISA: cp.async + ldmatrix + bf16 mma.sync)
// ===========================================================================
__device__ __forceinline__ void cp16(uint32_t saddr, const void* g) {
    asm volatile("cp.async.cg.shared.global [%0], [%1], 16;" :: "r"(saddr), "l"(g));
}
#define CP_COMMIT() asm volatile("cp.async.commit_group;" ::: "memory")
#define CP_WAIT2()  asm volatile("cp.async.wait_group 2;" ::: "memory")
#define CP_WAIT1()  asm volatile("cp.async.wait_group 1;" ::: "memory")
#define CP_WAIT0()  asm volatile("cp.async.wait_group 0;" ::: "memory")

__device__ __forceinline__ void ldsm4(uint32_t* r, uint32_t addr) {
    asm volatile("ldmatrix.sync.aligned.m8n8.x4.shared.b16 {%0,%1,%2,%3}, [%4];"
                 : "=r"(r[0]), "=r"(r[1]), "=r"(r[2]), "=r"(r[3]) : "r"(addr));
}
__device__ __forceinline__ void mma_bf16(float* d, const uint32_t* a, const uint32_t* b) {
    asm volatile(
        "mma.sync.aligned.m16n8k16.row.col.f32.bf16.bf16.f32 "
        "{%0,%1,%2,%3},{%4,%5,%6,%7},{%8,%9},{%0,%1,%2,%3};"
        : "+f"(d[0]), "+f"(d[1]), "+f"(d[2]), "+f"(d[3])
        : "r"(a[0]), "r"(a[1]), "r"(a[2]), "r"(a[3]), "r"(b[0]), "r"(b[1]));
}
// 64B-row swizzle selector (proven config)
__device__ __forceinline__ int swzs(int row) { return (row ^ (row >> 2)) & 3; }

// fp32 x8 -> bf16 x8: 2x float4 load + pack (used by prep and QKV A-path)
__device__ __forceinline__ uint4 ldcvt8(const float* p) {
    const float4 v0 = *(const float4*)p;
    const float4 v1 = *(const float4*)(p + 4);
    const __nv_bfloat162 a = __floats2bfloat162_rn(v0.x, v0.y);
    const __nv_bfloat162 b = __floats2bfloat162_rn(v0.z, v0.w);
    const __nv_bfloat162 c = __floats2bfloat162_rn(v1.x, v1.y);
    const __nv_bfloat162 d = __floats2bfloat162_rn(v1.z, v1.w);
    uint4 o;
    o.x = *(const uint32_t*)&a;  o.y = *(const uint32_t*)&b;
    o.z = *(const uint32_t*)&c;  o.w = *(const uint32_t*)&d;
    return o;
}

// ===========================================================================
// QKV GEMM: C = x(fp32, converted in-register) @ w_qkv(bf16)^T.
// CTA 128x128, BK=32. A: fp32 LDG + reg-convert + STS, 2-stage smem buffer.
// B: 4-stage cp.async ring (proven). Warp grid 4x2 (32x64), ldmatrix.
// Epilogue: QKV split — cols [0,512) bf16 -> g_qb; [512,1536) -> g_kvb.
// smem: A 2x8KB + B 4x8KB = 48KB dynamic.
// ===========================================================================
__device__ __forceinline__ void gemm_qkv(
    const float* __restrict__ X, const __nv_bfloat16* __restrict__ B,
    int N, int Kd, int bm, int bn, unsigned char* smem)
{
    const int tid  = threadIdx.x;
    const int warp = tid >> 5;
    const int lane = tid & 31;
    const int wm   = warp & 3;
    const int wn   = warp >> 2;
    const uint32_t sbase = (uint32_t)__cvta_generic_to_shared(smem);
    const uint32_t sAb   = sbase;            // 2 x 8KB
    const uint32_t sBb   = sbase + 16384;    // 4 x 8KB

    // fill mapping: 512 16B chunks per array per stage, 2 per thread
    const int r0 = tid >> 2,          c0 = tid & 3;
    const int r1 = (tid + 256) >> 2;
    const uint32_t d0 = r0 * 64 + ((c0 ^ swzs(r0)) << 4);
    const uint32_t d1 = r1 * 64 + ((c0 ^ swzs(r1)) << 4);
    const float* gA0 = X + (size_t)(bm + r0) * Kd + c0 * 8;   // fp32 source
    const float* gA1 = X + (size_t)(bm + r1) * Kd + c0 * 8;
    const __nv_bfloat16* gB0 = B + (size_t)(bn + r0) * Kd + c0 * 8;
    const __nv_bfloat16* gB1 = B + (size_t)(bn + r1) * Kd + c0 * 8;

    // ldmatrix lane addressing
    const int l7 = lane & 7;
    int rowA[2], swA[2];
    #pragma unroll
    for (int am = 0; am < 2; am++) {
        const int row = wm * 32 + am * 16 + ((lane >> 3) & 1) * 8 + l7;
        rowA[am] = row * 64;  swA[am] = swzs(row);
    }
    const int cselA = lane >> 4;
    int rowB[4], swB[4];
    #pragma unroll
    for (int bp = 0; bp < 4; bp++) {
        const int row = wn * 64 + bp * 16 + ((lane >> 4) << 3) + l7;
        rowB[bp] = row * 64;  swB[bp] = swzs(row);
    }
    const int cselB = (lane >> 3) & 1;

    float acc[2][8][4];
    #pragma unroll
    for (int i = 0; i < 2; i++)
        #pragma unroll
        for (int j = 0; j < 8; j++)
            #pragma unroll
            for (int q = 0; q < 4; q++) acc[i][j][q] = 0.f;

    const int T = Kd >> 5;   // BK = 32; T = 16

    // ---- prologue ----
    // A tile 0 -> buf0 (visible after first barrier)
    {
        const uint4 a0 = ldcvt8(gA0);
        const uint4 a1 = ldcvt8(gA1);
        *(uint4*)(smem + d0) = a0;
        *(uint4*)(smem + d1) = a1;
    }
    // stage A tile 1 in regs (bf16-packed)
    uint4 aS0 = ldcvt8(gA0 + 32);
    uint4 aS1 = ldcvt8(gA1 + 32);
    // B stages 0..2
    #pragma unroll
    for (int s = 0; s < 3; ++s) {
        const int k0 = s << 5;
        const uint32_t sb = sBb + s * 8192;
        cp16(sb + d0, gB0 + k0);  cp16(sb + d1, gB1 + k0);
        CP_COMMIT();
    }

    for (int t = 0; t < T; ++t) {
        if (t + 3 <= T) CP_WAIT2();
        else if (t + 2 == T) CP_WAIT1();
        else CP_WAIT0();
        __syncthreads();

        if (t + 1 < T) {      // STS staged A tile t+1 into buf (t+1)&1
            unsigned char* ab = smem + ((t + 1) & 1) * 8192;
            *(uint4*)(ab + d0) = aS0;
            *(uint4*)(ab + d1) = aS1;
        }
        if (t + 2 < T) {      // LDG+CVT A tile t+2 into regs
            const int k0 = (t + 2) << 5;
            aS0 = ldcvt8(gA0 + k0);
            aS1 = ldcvt8(gA1 + k0);
        }
        if (t + 3 < T) {      // B prefetch
            const int s2 = (t + 3) & 3;
            const int k0 = (t + 3) << 5;
            const uint32_t sb = sBb + s2 * 8192;
            cp16(sb + d0, gB0 + k0);  cp16(sb + d1, gB1 + k0);
            CP_COMMIT();
        }

        const uint32_t sa = sAb + (t & 1) * 8192;
        const uint32_t sb = sBb + (t & 3) * 8192;
        #pragma unroll
        for (int g = 0; g < 2; ++g) {
            uint32_t af[2][4], bf[4][4];
            #pragma unroll
            for (int am = 0; am < 2; am++)
                ldsm4(af[am], sa + rowA[am] + ((((g << 1) | cselA) ^ swA[am]) << 4));
            #pragma unroll
            for (int bp = 0; bp < 4; bp++)
                ldsm4(bf[bp], sb + rowB[bp] + ((((g << 1) | cselB) ^ swB[bp]) << 4));
            #pragma unroll
            for (int am = 0; am < 2; am++)
                #pragma unroll
                for (int nb = 0; nb < 8; nb++)
                    mma_bf16(acc[am][nb], af[am], &bf[nb >> 1][(nb & 1) << 1]);
        }
    }

    // ---- epilogue: QKV split bf16 ----
    const int r4 = lane >> 2, c4 = lane & 3;
    #pragma unroll
    for (int am = 0; am < 2; ++am) {
        const int m0 = bm + wm * 32 + am * 16 + r4;
        #pragma unroll
        for (int nb = 0; nb < 8; ++nb) {
            const int n0 = bn + wn * 64 + nb * 8 + c4 * 2;
            const float2 v01 = make_float2(acc[am][nb][0], acc[am][nb][1]);
            const float2 v23 = make_float2(acc[am][nb][2], acc[am][nb][3]);
            if (bn < DMODEL) {
                *(__nv_bfloat162*)(g_qb + (size_t)m0 * DMODEL + n0)
                    = __floats2bfloat162_rn(v01.x, v01.y);
                *(__nv_bfloat162*)(g_qb + (size_t)(m0 + 8) * DMODEL + n0)
                    = __floats2bfloat162_rn(v23.x, v23.y);
            } else {
                const int nc = n0 - DMODEL;
                *(__nv_bfloat162*)(g_kvb + (size_t)m0 * (2 * DMODEL) + nc)
                    = __floats2bfloat162_rn(v01.x, v01.y);
                *(__nv_bfloat162*)(g_kvb + (size_t)(m0 + 8) * (2 * DMODEL) + nc)
                    = __floats2bfloat162_rn(v23.x, v23.y);
            }
        }
    }
}

// ===========================================================================
// bf16 NT GEMM body, CTA 64x128, BK=32, 4-stage ring — proj variant (proven).
// Warp grid 2(m) x 4(n), warp tile 32x32. Epilogue: C += bias[n]+resid.
// smem: 4 stages x (4KB A + 8KB B) = 48KB dynamic.
// ===========================================================================
__device__ __forceinline__ void gemm_body64(
    const __nv_bfloat16* __restrict__ A, const __nv_bfloat16* __restrict__ B,
    float* __restrict__ C, int N, int Kd,
    const float* __restrict__ bias, const float* __restrict__ resid,
    int bm, int bn, unsigned char* smem)
{
    const int tid  = threadIdx.x;
    const int warp = tid >> 5;
    const int lane = tid & 31;
    const int wm   = warp & 1;
    const int wn   = warp >> 1;
    const uint32_t sbase = (uint32_t)__cvta_generic_to_shared(smem);

    const int ra = tid >> 2, ca = tid & 3;
    const uint32_t da = ra * 64 + ((ca ^ swzs(ra)) << 4);
    const __nv_bfloat16* gA = A + (size_t)(bm + ra) * Kd + ca * 8;
    const int r1 = (tid + 256) >> 2;
    const uint32_t d0 = da;
    const uint32_t d1 = r1 * 64 + ((ca ^ swzs(r1)) << 4);
    const __nv_bfloat16* gB0 = B + (size_t)(bn + ra) * Kd + ca * 8;
    const __nv_bfloat16* gB1 = B + (size_t)(bn + r1) * Kd + ca * 8;

    const int l7 = lane & 7;
    int rowA[2], swA[2];
    #pragma unroll
    for (int am = 0; am < 2; am++) {
        const int row = wm * 32 + am * 16 + ((lane >> 3) & 1) * 8 + l7;
        rowA[am] = row * 64;  swA[am] = swzs(row);
    }
    const int cselA = lane >> 4;
    int rowB[2], swB[2];
    #pragma unroll
    for (int bp = 0; bp < 2; bp++) {
        const int row = wn * 32 + bp * 16 + ((lane >> 4) << 3) + l7;
        rowB[bp] = row * 64;  swB[bp] = swzs(row);
    }
    const int cselB = (lane >> 3) & 1;

    float acc[2][4][4];
    #pragma unroll
    for (int i = 0; i < 2; i++)
        #pragma unroll
        for (int j = 0; j < 4; j++)
            #pragma unroll
            for (int q = 0; q < 4; q++) acc[i][j][q] = 0.f;

    const int T = Kd >> 5;   // BK = 32

    #pragma unroll
    for (int s = 0; s < 3; ++s) {
        const int k0 = s << 5;
        const uint32_t sa = sbase + s * 12288, sb = sa + 4096;
        cp16(sa + da, gA + k0);
        cp16(sb + d0, gB0 + k0);  cp16(sb + d1, gB1 + k0);
        CP_COMMIT();
    }

    for (int t = 0; t < T; ++t) {
        if (t + 3 <= T) CP_WAIT2();
        else if (t + 2 == T) CP_WAIT1();
        else CP_WAIT0();
        __syncthreads();

        if (t + 3 < T) {
            const int s2 = (t + 3) & 3;
            const int k0 = (t + 3) << 5;
            const uint32_t sa = sbase + s2 * 12288, sb = sa + 4096;
            cp16(sa + da, gA + k0);
            cp16(sb + d0, gB0 + k0);  cp16(sb + d1, gB1 + k0);
            CP_COMMIT();
        }

        const uint32_t sa = sbase + (t & 3) * 12288, sb = sa + 4096;
        #pragma unroll
        for (int g = 0; g < 2; ++g) {
            uint32_t af[2][4], bf[2][4];
            #pragma unroll
            for (int am = 0; am < 2; am++)
                ldsm4(af[am], sa + rowA[am] + ((((g << 1) | cselA) ^ swA[am]) << 4));
            #pragma unroll
            for (int bp = 0; bp < 2; bp++)
                ldsm4(bf[bp], sb + rowB[bp] + ((((g << 1) | cselB) ^ swB[bp]) << 4));
            #pragma unroll
            for (int am = 0; am < 2; am++)
                #pragma unroll
                for (int nb = 0; nb < 4; nb++)
                    mma_bf16(acc[am][nb], af[am], &bf[nb >> 1][(nb & 1) << 1]);
        }
    }

    // ---- epilogue: bias + residual, fp32 out ----
    const int r4 = lane >> 2, c4 = lane & 3;
    #pragma unroll
    for (int am = 0; am < 2; ++am) {
        const int m0 = bm + wm * 32 + am * 16 + r4;
        #pragma unroll
        for (int nb = 0; nb < 4; ++nb) {
            const int n0 = bn + wn * 32 + nb * 8 + c4 * 2;
            float2 v01 = make_float2(acc[am][nb][0], acc[am][nb][1]);
            float2 v23 = make_float2(acc[am][nb][2], acc[am][nb][3]);
            const float2 bz = *(const float2*)(bias + n0);
            const float2 q0 = *(const float2*)(resid + (size_t)m0 * N + n0);
            const float2 q1 = *(const float2*)(resid + (size_t)(m0 + 8) * N + n0);
            v01.x += bz.x + q0.x;  v01.y += bz.y + q0.y;
            v23.x += bz.x + q1.x;  v23.y += bz.y + q1.y;
            *(float2*)(C + (size_t)m0 * N + n0)       = v01;
            *(float2*)(C + (size_t)(m0 + 8) * N + n0) = v23;
        }
    }
}

// ===========================================================================
// prep kernel: blocks 0..1 build the per-batch spatial grid; remaining
// blocks convert w_qkv and w_proj fp32 -> bf16 (x conversion eliminated —
// the QKV GEMM now reads fp32 x directly and converts in-register).
// ===========================================================================
__global__ void __launch_bounds__(1024) prep_kernel(
    const float* __restrict__ coords,
    const float* __restrict__ w_qkv, const float* __restrict__ w_proj)
{
    if (blockIdx.x < BATCH) {
        const int b = blockIdx.x;
        __shared__ int cnt[CELLS];
        __shared__ int part[1024];
        const int t = threadIdx.x;
        #pragma unroll
        for (int i = t; i < CELLS; i += 1024) cnt[i] = 0;
        __syncthreads();

        const float2* cb = (const float2*)coords + (size_t)b * NTOK;
        int pcid[4]; float2 pc[4];
        #pragma unroll
        for (int j = 0; j < 4; j++) {
            const int p = t + j * 1024;
            const float2 c = cb[p];
            const int cx = min(GRID - 1, max(0, (int)(c.x * INVCELL)));
            const int cy = min(GRID - 1, max(0, (int)(c.y * INVCELL)));
            pcid[j] = cy * GRID + cx;  pc[j] = c;
            atomicAdd(&cnt[pcid[j]], 1);
        }
        __syncthreads();

        const int c0 = cnt[t*4], c1 = cnt[t*4+1], c2 = cnt[t*4+2], c3 = cnt[t*4+3];
        const int lsum = c0 + c1 + c2 + c3;
        part[t] = lsum;
        __syncthreads();
        for (int off = 1; off < 1024; off <<= 1) {
            const int v = (t >= off) ? part[t - off] : 0;
            __syncthreads();
            part[t] += v;
            __syncthreads();
        }
        const int excl = part[t] - lsum;
        const int s0 = excl, s1 = excl + c0, s2 = s1 + c1, s3 = s2 + c2;
        cnt[t*4] = s0; cnt[t*4+1] = s1; cnt[t*4+2] = s2; cnt[t*4+3] = s3;
        int* csg = g_cellstart + b * (CELLS + 1);
        csg[t*4] = s0; csg[t*4+1] = s1; csg[t*4+2] = s2; csg[t*4+3] = s3;
        if (t == 1023) csg[CELLS] = NTOK;
        __syncthreads();

        #pragma unroll
        for (int j = 0; j < 4; j++) {
            const int pos = atomicAdd(&cnt[pcid[j]], 1);
            g_scoord[b * NTOK + pos] = pc[j];
            g_sidx[b * NTOK + pos]   = t + j * 1024;
        }
    } else {
        const long stride = (long)(gridDim.x - BATCH) * 1024;
        const long base   = (long)(blockIdx.x - BATCH) * 1024 + threadIdx.x;

        constexpr long W8 = (long)3 * DMODEL * DMODEL / 8;   // 98304 items
        const float* ws = w_qkv;
        uint4* wd = (uint4*)g_wqb;
        for (long i = base; i < W8; i += stride) wd[i] = ldcvt8(ws + i * 8);

        constexpr long P8 = (long)DMODEL * DMODEL / 8;       // 32768 items
        const float* ps = w_proj;
        uint4* pd = (uint4*)g_wpb;
        for (long i = base; i < P8; i += stride) pd[i] = ldcvt8(ps + i * 8);
    }
}

// ===========================================================================
// grid kNN query: one thread per query; exact top-9 via ring expansion with
// cell-box lower-bound pruning (proven fastest config).
// ===========================================================================
__device__ __forceinline__ void scan_cell(
    int X, int Y, float qx, float qy,
    const int* __restrict__ cs, const float2* __restrict__ sc,
    const int* __restrict__ si,
    float (&d9)[KNN], int (&i9)[KNN], float& dmax, int& imax)
{
    const float lx = X * CELLSZ, ly = Y * CELLSZ;
    const float ddx = fmaxf(0.f, fmaxf(lx - qx, qx - (lx + CELLSZ)));
    const float ddy = fmaxf(0.f, fmaxf(ly - qy, qy - (ly + CELLSZ)));
    if (ddx * ddx + ddy * ddy >= dmax) return;
    const int cid = Y * GRID + X;
    const int s1 = cs[cid + 1];
    for (int s = cs[cid]; s < s1; ++s) {
        const float2 p = sc[s];
        const float dx = p.x - qx, dy = p.y - qy;
        const float d2 = dx * dx + dy * dy;
        if (d2 < dmax) {
            const int idx = si[s];
            #pragma unroll
            for (int j = 0; j < KNN; j++)
                if (j == imax) { d9[j] = d2; i9[j] = idx; }
            dmax = d9[0]; imax = 0;
            #pragma unroll
            for (int j = 1; j < KNN; j++)
                if (d9[j] > dmax) { dmax = d9[j]; imax = j; }
        }
    }
}

__device__ __forceinline__ void knn_query(const float* __restrict__ coords, int q)
{
    const int b = q >> 12, n = q & (NTOK - 1);
    const float2 qc = ((const float2*)coords)[(size_t)b * NTOK + n];
    const float qx = qc.x, qy = qc.y;
    const int cx = min(GRID - 1, max(0, (int)(qx * INVCELL)));
    const int cy = min(GRID - 1, max(0, (int)(qy * INVCELL)));
    const int*    cs = g_cellstart + b * (CELLS + 1);
    const float2* sc = g_scoord + b * NTOK;
    const int*    si = g_sidx + b * NTOK;

    float d9[KNN]; int i9[KNN];
    #pragma unroll
    for (int j = 0; j < KNN; j++) { d9[j] = 3.4e38f; i9[j] = 0; }
    float dmax = 3.4e38f; int imax = 0;

    for (int r = 0; r < GRID; ++r) {
        const int xlo = max(cx - r, 0), xhi = min(cx + r, GRID - 1);
        if (r == 0) {
            scan_cell(cx, cy, qx, qy, cs, sc, si, d9, i9, dmax, imax);
        } else {
            if (cy - r >= 0)
                for (int X = xlo; X <= xhi; X++)
                    scan_cell(X, cy - r, qx, qy, cs, sc, si, d9, i9, dmax, imax);
            if (cy + r <= GRID - 1)
                for (int X = xlo; X <= xhi; X++)
                    scan_cell(X, cy + r, qx, qy, cs, sc, si, d9, i9, dmax, imax);
            const int yl = max(cy - r + 1, 0), yh = min(cy + r - 1, GRID - 1);
            if (cx - r >= 0)
                for (int Y = yl; Y <= yh; Y++)
                    scan_cell(cx - r, Y, qx, qy, cs, sc, si, d9, i9, dmax, imax);
            if (cx + r <= GRID - 1)
                for (int Y = yl; Y <= yh; Y++)
                    scan_cell(cx + r, Y, qx, qy, cs, sc, si, d9, i9, dmax, imax);
        }
        const float rs = r * CELLSZ;
        if (rs * rs >= dmax) break;
    }
    #pragma unroll
    for (int j = 0; j < KNN; j++) g_nn[(size_t)q * KNN + j] = i9[j];
}

// ===========================================================================
// Fused launch: blocks [0,32) = kNN (thread-per-query, FIRST so it hides
// under the GEMM waves); blocks [32, 800) = QKV GEMM tiles (128x128).
// ===========================================================================
#define KNN_BLOCKS 32

__global__ void __launch_bounds__(256, 2) qkv_knn_kernel(
    const float* __restrict__ coords, const float* __restrict__ x)
{
    extern __shared__ __align__(128) unsigned char smem[];
    if (blockIdx.x < KNN_BLOCKS) {
        knn_query(coords, blockIdx.x * 256 + threadIdx.x);
    } else {
        const int idx = blockIdx.x - KNN_BLOCKS;
        gemm_qkv(x, g_wqb, 3 * DMODEL, DMODEL,
                 (idx / 12) * 128, (idx % 12) * 128, smem);
    }
}

__global__ void __launch_bounds__(256, 2) proj_kernel(
    float* __restrict__ C, const float* __restrict__ bias, const float* __restrict__ resid)
{
    extern __shared__ __align__(128) unsigned char smem[];
    gemm_body64(g_attnb, g_wpb, C, DMODEL, DMODEL, bias, resid,
                blockIdx.y * 64, blockIdx.x * 128, smem);
}

// ---------------------------------------------------------------------------
// Attention: one WARP per token, full-row vectorized (proven config).
// Lane l owns dims [16l, 16l+16); head logit via 2-shfl reduce in 4-lane group.
// Fused exact-erf GELU; bf16 out. No smem, no block sync.
// ---------------------------------------------------------------------------
__device__ __forceinline__ float dot8_bf16(uint4 a, uint4 b) {
    const uint32_t* pa = (const uint32_t*)&a;
    const uint32_t* pb = (const uint32_t*)&b;
    float s = 0.f;
    #pragma unroll
    for (int i = 0; i < 4; i++) {
        const float2 fa = __bfloat1622float2(*(const __nv_bfloat162*)&pa[i]);
        const float2 fb = __bfloat1622float2(*(const __nv_bfloat162*)&pb[i]);
        s = fmaf(fa.x, fb.x, s);
        s = fmaf(fa.y, fb.y, s);
    }
    return s;
}
__device__ __forceinline__ void fma8_bf16(float* acc, float w, uint4 v) {
    const uint32_t* pv = (const uint32_t*)&v;
    #pragma unroll
    for (int i = 0; i < 4; i++) {
        const float2 fv = __bfloat1622float2(*(const __nv_bfloat162*)&pv[i]);
        acc[2*i]   = fmaf(w, fv.x, acc[2*i]);
        acc[2*i+1] = fmaf(w, fv.y, acc[2*i+1]);
    }
}

__global__ void __launch_bounds__(256) attn_kernel()
{
    const int r    = blockIdx.x * 8 + (threadIdx.x >> 5);   // token 0..8191
    const int lane = threadIdx.x & 31;
    const int b    = r >> 12;

    int idxv = 0;
    if (lane < KNN) idxv = (b << 12) + g_nn[(size_t)r * KNN + lane];
    int idx[KNN];
    #pragma unroll
    for (int j = 0; j < KNN; j++) idx[j] = __shfl_sync(0xffffffffu, idxv, j);

    const uint4* qrow = (const uint4*)(g_qb + (size_t)r * DMODEL) + lane * 2;
    const uint4 q0 = qrow[0], q1 = qrow[1];

    float logit[KNN];
    #pragma unroll
    for (int j = 0; j < KNN; j++) {
        const uint4* krow = (const uint4*)(g_kvb + (size_t)idx[j] * (2 * DMODEL)) + lane * 2;
        const uint4 k0 = krow[0], k1 = krow[1];
        float p = dot8_bf16(q0, k0) + dot8_bf16(q1, k1);
        p += __shfl_xor_sync(0xffffffffu, p, 1);
        p += __shfl_xor_sync(0xffffffffu, p, 2);
        logit[j] = p * 0.125f;
    }

    float mx = logit[0];
    #pragma unroll
    for (int j = 1; j < KNN; j++) mx = fmaxf(mx, logit[j]);
    float sum = 0.f;
    #pragma unroll
    for (int j = 0; j < KNN; j++) { logit[j] = __expf(logit[j] - mx); sum += logit[j]; }
    const float inv = 1.f / sum;

    float acc[16];
    #pragma unroll
    for (int i = 0; i < 16; i++) acc[i] = 0.f;
    #pragma unroll
    for (int j = 0; j < KNN; j++) {
        const uint4* vrow = (const uint4*)(g_kvb + (size_t)idx[j] * (2 * DMODEL) + DMODEL)
                            + lane * 2;
        const uint4 v0 = vrow[0], v1 = vrow[1];
        const float w = logit[j] * inv;
        fma8_bf16(acc,     w, v0);
        fma8_bf16(acc + 8, w, v1);
    }

    uint4 o[2];
    uint32_t* po = (uint32_t*)o;
    #pragma unroll
    for (int i = 0; i < 8; i++) {
        float a = acc[2*i],   bq = acc[2*i+1];
        a  = 0.5f * a  * (1.f + erff(a  * 0.70710678118654752f));
        bq = 0.5f * bq * (1.f + erff(bq * 0.70710678118654752f));
        const __nv_bfloat162 pk = __floats2bfloat162_rn(a, bq);
        po[i] = *(const uint32_t*)&pk;
    }
    uint4* orow = (uint4*)(g_attnb + (size_t)r * DMODEL) + lane * 2;
    orow[0] = o[0];
    orow[1] = o[1];
}

// ---------------------------------------------------------------------------
// kernel_launch: x, coords, w_qkv, w_proj, b_proj  ->  out (fp32, B*N*D)
// ---------------------------------------------------------------------------
extern "C" void kernel_launch(void* const* d_in, const int* in_sizes, int n_in,
                              void* d_out, int out_size)
{
    const float* x      = (const float*)d_in[0];
    const float* coords = (const float*)d_in[1];
    const float* w_qkv  = (const float*)d_in[2];
    const float* w_proj = (const float*)d_in[3];
    const float* b_proj = (const float*)d_in[4];
    float* out = (float*)d_out;

    constexpr int SMEM_QKV  = 49152;   // A 2x8KB + B 4x8KB
    constexpr int SMEM_PROJ = 49152;   // 4 x 12KB
    cudaFuncSetAttribute(qkv_knn_kernel, cudaFuncAttributeMaxDynamicSharedMemorySize, SMEM_QKV);
    cudaFuncSetAttribute(proj_kernel,    cudaFuncAttributeMaxDynamicSharedMemorySize, SMEM_PROJ);

    // 1) grid build (2 blocks) + w_qkv/w_proj conversion (~6.5MB, one wave)
    prep_kernel<<<BATCH + 130, 1024>>>(coords, w_qkv, w_proj);

    // 2) kNN (32 blocks, first) + QKV GEMM (768 blocks, fp32-x direct)
    qkv_knn_kernel<<<KNN_BLOCKS + 768, 256, SMEM_QKV>>>(coords, x);

    // 3) neighbor attention + GELU (warp-per-token, bf16 out)
    attn_kernel<<<MROWS / 8, 256>>>();

    // 4) output projection + bias + residual (512 CTAs of 64x128)
    {
        dim3 grid(DMODEL / 128, MROWS / 64);
        proj_kernel<<<grid, 256, SMEM_PROJ>>>(out, b_proj, x);
    }
}

// round 17
// speedup vs baseline: 1.1537x; 1.1537x over previous
#include <cuda_runtime.h>
#include <cuda_bf16.h>
#include <math.h>
#include <stdint.h>
#include <stddef.h>

// Problem constants (fixed by the reference setup_inputs)
#define BATCH  2
#define NTOK   4096
#define DMODEL 512
#define HEADS  8
#define HDIM   64
#define KNN    9
#define MROWS  (BATCH * NTOK)          // 8192
#define GRID   64
#define CELLS  (GRID * GRID)
#define CELLSZ 1.5625f                 // 100/64
#define INVCELL 0.64f                  // 64/100

// Scratch (static __device__ arrays: allocation-free, harness-legal)
__device__ __nv_bfloat16  g_qb[(size_t)MROWS * DMODEL];          // bf16 Q
__device__ __nv_bfloat16  g_kvb[(size_t)MROWS * 2 * DMODEL];     // bf16 K|V
__device__ __nv_bfloat16  g_attnb[(size_t)MROWS * DMODEL];       // bf16 GELU(attn)
__device__ __nv_bfloat16  g_xb[(size_t)MROWS * DMODEL];          // bf16 x
__device__ __nv_bfloat16  g_wqb[(size_t)3 * DMODEL * DMODEL];    // bf16 w_qkv
__device__ __nv_bfloat16  g_wpb[(size_t)DMODEL * DMODEL];        // bf16 w_proj
__device__ int            g_nn[(size_t)MROWS * KNN];
__device__ int            g_cellstart[BATCH * (CELLS + 1)];
__device__ float2         g_scoord[BATCH * NTOK];
__device__ int            g_sidx[BATCH * NTOK];

// ===========================================================================
// PTX helpers (base sm_103 ISA: cp.async + ldmatrix + bf16 mma.sync)
// ===========================================================================
__device__ __forceinline__ void cp16(uint32_t saddr, const void* g) {
    asm volatile("cp.async.cg.shared.global [%0], [%1], 16;" :: "r"(saddr), "l"(g));
}
#define CP_COMMIT() asm volatile("cp.async.commit_group;" ::: "memory")
#define CP_WAIT2()  asm volatile("cp.async.wait_group 2;" ::: "memory")
#define CP_WAIT1()  asm volatile("cp.async.wait_group 1;" ::: "memory")
#define CP_WAIT0()  asm volatile("cp.async.wait_group 0;" ::: "memory")

__device__ __forceinline__ void ldsm4(uint32_t* r, uint32_t addr) {
    asm volatile("ldmatrix.sync.aligned.m8n8.x4.shared.b16 {%0,%1,%2,%3}, [%4];"
                 : "=r"(r[0]), "=r"(r[1]), "=r"(r[2]), "=r"(r[3]) : "r"(addr));
}
__device__ __forceinline__ void mma_bf16(float* d, const uint32_t* a, const uint32_t* b) {
    asm volatile(
        "mma.sync.aligned.m16n8k16.row.col.f32.bf16.bf16.f32 "
        "{%0,%1,%2,%3},{%4,%5,%6,%7},{%8,%9},{%0,%1,%2,%3};"
        : "+f"(d[0]), "+f"(d[1]), "+f"(d[2]), "+f"(d[3])
        : "r"(a[0]), "r"(a[1]), "r"(a[2]), "r"(a[3]), "r"(b[0]), "r"(b[1]));
}
// 64B-row swizzle selector (proven config)
__device__ __forceinline__ int swzs(int row) { return (row ^ (row >> 2)) & 3; }

// fp32 x8 -> bf16 x8 converter (32B load, 16B store)
__device__ __forceinline__ uint4 cvt2f4(const float4* src, long i) {
    const float4 v0 = src[2 * i];
    const float4 v1 = src[2 * i + 1];
    const __nv_bfloat162 a = __floats2bfloat162_rn(v0.x, v0.y);
    const __nv_bfloat162 b = __floats2bfloat162_rn(v0.z, v0.w);
    const __nv_bfloat162 c = __floats2bfloat162_rn(v1.x, v1.y);
    const __nv_bfloat162 d = __floats2bfloat162_rn(v1.z, v1.w);
    uint4 o;
    o.x = *(const uint32_t*)&a;  o.y = *(const uint32_t*)&b;
    o.z = *(const uint32_t*)&c;  o.w = *(const uint32_t*)&d;
    return o;
}

// ===========================================================================
// bf16 NT GEMM body, CTA 128x128, BK=32, 4-stage ring (proven config).
// QKV split epilogue: cols [0,512) bf16 -> g_qb; [512,1536) -> g_kvb.
// smem: 4 stages x 16KB = 64KB dynamic.
// ===========================================================================
__device__ __forceinline__ void gemm_body128(
    const __nv_bfloat16* __restrict__ A, const __nv_bfloat16* __restrict__ B,
    int N, int Kd, int bm, int bn, unsigned char* smem)
{
    const int tid  = threadIdx.x;
    const int warp = tid >> 5;
    const int lane = tid & 31;
    const int wm   = warp & 3;
    const int wn   = warp >> 2;
    const uint32_t sbase = (uint32_t)__cvta_generic_to_shared(smem);

    const int r0 = tid >> 2,          c0 = tid & 3;
    const int r1 = (tid + 256) >> 2;
    const uint32_t d0 = r0 * 64 + ((c0 ^ swzs(r0)) << 4);
    const uint32_t d1 = r1 * 64 + ((c0 ^ swzs(r1)) << 4);
    const __nv_bfloat16* gA0 = A + (size_t)(bm + r0) * Kd + c0 * 8;
    const __nv_bfloat16* gA1 = A + (size_t)(bm + r1) * Kd + c0 * 8;
    const __nv_bfloat16* gB0 = B + (size_t)(bn + r0) * Kd + c0 * 8;
    const __nv_bfloat16* gB1 = B + (size_t)(bn + r1) * Kd + c0 * 8;

    const int l7 = lane & 7;
    int rowA[2], swA[2];
    #pragma unroll
    for (int am = 0; am < 2; am++) {
        const int row = wm * 32 + am * 16 + ((lane >> 3) & 1) * 8 + l7;
        rowA[am] = row * 64;  swA[am] = swzs(row);
    }
    const int cselA = lane >> 4;
    int rowB[4], swB[4];
    #pragma unroll
    for (int bp = 0; bp < 4; bp++) {
        const int row = wn * 64 + bp * 16 + ((lane >> 4) << 3) + l7;
        rowB[bp] = row * 64;  swB[bp] = swzs(row);
    }
    const int cselB = (lane >> 3) & 1;

    float acc[2][8][4];
    #pragma unroll
    for (int i = 0; i < 2; i++)
        #pragma unroll
        for (int j = 0; j < 8; j++)
            #pragma unroll
            for (int q = 0; q < 4; q++) acc[i][j][q] = 0.f;

    const int T = Kd >> 5;   // BK = 32

    #pragma unroll
    for (int s = 0; s < 3; ++s) {
        const int k0 = s << 5;
        const uint32_t sa = sbase + s * 16384, sb = sa + 8192;
        cp16(sa + d0, gA0 + k0);  cp16(sa + d1, gA1 + k0);
        cp16(sb + d0, gB0 + k0);  cp16(sb + d1, gB1 + k0);
        CP_COMMIT();
    }

    for (int t = 0; t < T; ++t) {
        if (t + 3 <= T) CP_WAIT2();
        else if (t + 2 == T) CP_WAIT1();
        else CP_WAIT0();
        __syncthreads();

        if (t + 3 < T) {
            const int s2 = (t + 3) & 3;
            const int k0 = (t + 3) << 5;
            const uint32_t sa = sbase + s2 * 16384, sb = sa + 8192;
            cp16(sa + d0, gA0 + k0);  cp16(sa + d1, gA1 + k0);
            cp16(sb + d0, gB0 + k0);  cp16(sb + d1, gB1 + k0);
            CP_COMMIT();
        }

        const uint32_t sa = sbase + (t & 3) * 16384, sb = sa + 8192;
        #pragma unroll
        for (int g = 0; g < 2; ++g) {
            uint32_t af[2][4], bf[4][4];
            #pragma unroll
            for (int am = 0; am < 2; am++)
                ldsm4(af[am], sa + rowA[am] + ((((g << 1) | cselA) ^ swA[am]) << 4));
            #pragma unroll
            for (int bp = 0; bp < 4; bp++)
                ldsm4(bf[bp], sb + rowB[bp] + ((((g << 1) | cselB) ^ swB[bp]) << 4));
            #pragma unroll
            for (int am = 0; am < 2; am++)
                #pragma unroll
                for (int nb = 0; nb < 8; nb++)
                    mma_bf16(acc[am][nb], af[am], &bf[nb >> 1][(nb & 1) << 1]);
        }
    }

    // ---- epilogue: QKV split bf16 ----
    const int r4 = lane >> 2, c4 = lane & 3;
    #pragma unroll
    for (int am = 0; am < 2; ++am) {
        const int m0 = bm + wm * 32 + am * 16 + r4;
        #pragma unroll
        for (int nb = 0; nb < 8; ++nb) {
            const int n0 = bn + wn * 64 + nb * 8 + c4 * 2;
            const float2 v01 = make_float2(acc[am][nb][0], acc[am][nb][1]);
            const float2 v23 = make_float2(acc[am][nb][2], acc[am][nb][3]);
            if (bn < DMODEL) {
                *(__nv_bfloat162*)(g_qb + (size_t)m0 * DMODEL + n0)
                    = __floats2bfloat162_rn(v01.x, v01.y);
                *(__nv_bfloat162*)(g_qb + (size_t)(m0 + 8) * DMODEL + n0)
                    = __floats2bfloat162_rn(v23.x, v23.y);
            } else {
                const int nc = n0 - DMODEL;
                *(__nv_bfloat162*)(g_kvb + (size_t)m0 * (2 * DMODEL) + nc)
                    = __floats2bfloat162_rn(v01.x, v01.y);
                *(__nv_bfloat162*)(g_kvb + (size_t)(m0 + 8) * (2 * DMODEL) + nc)
                    = __floats2bfloat162_rn(v23.x, v23.y);
            }
        }
    }
}

// ===========================================================================
// bf16 NT GEMM body, CTA 64x128, BK=32, 4-stage ring — proj variant.
// Warp grid 2(m) x 4(n), warp tile 32x32. Epilogue: C += bias[n]+resid,
// with the resid tile PREFETCHED into smem via its own cp.async group
// (committed after the 3 ring prologue stages; retired by the t=2 ring wait).
// smem: ring 4 x 12KB = 48KB + resid 64 x 132 floats (33792B) = 82944B.
// ===========================================================================
#define PROJ_RING_BYTES   49152
#define PROJ_RESID_STRIDE 132        // floats per padded row (conflict-free)
#define PROJ_SMEM_TOTAL   (PROJ_RING_BYTES + 64 * PROJ_RESID_STRIDE * 4)

__device__ __forceinline__ void gemm_body64(
    const __nv_bfloat16* __restrict__ A, const __nv_bfloat16* __restrict__ B,
    float* __restrict__ C, int N, int Kd,
    const float* __restrict__ bias, const float* __restrict__ resid,
    int bm, int bn, unsigned char* smem)
{
    const int tid  = threadIdx.x;
    const int warp = tid >> 5;
    const int lane = tid & 31;
    const int wm   = warp & 1;
    const int wn   = warp >> 1;
    const uint32_t sbase = (uint32_t)__cvta_generic_to_shared(smem);
    const uint32_t sresid = sbase + PROJ_RING_BYTES;

    const int ra = tid >> 2, ca = tid & 3;
    const uint32_t da = ra * 64 + ((ca ^ swzs(ra)) << 4);
    const __nv_bfloat16* gA = A + (size_t)(bm + ra) * Kd + ca * 8;
    const int r1 = (tid + 256) >> 2;
    const uint32_t d0 = da;
    const uint32_t d1 = r1 * 64 + ((ca ^ swzs(r1)) << 4);
    const __nv_bfloat16* gB0 = B + (size_t)(bn + ra) * Kd + ca * 8;
    const __nv_bfloat16* gB1 = B + (size_t)(bn + r1) * Kd + ca * 8;

    const int l7 = lane & 7;
    int rowA[2], swA[2];
    #pragma unroll
    for (int am = 0; am < 2; am++) {
        const int row = wm * 32 + am * 16 + ((lane >> 3) & 1) * 8 + l7;
        rowA[am] = row * 64;  swA[am] = swzs(row);
    }
    const int cselA = lane >> 4;
    int rowB[2], swB[2];
    #pragma unroll
    for (int bp = 0; bp < 2; bp++) {
        const int row = wn * 32 + bp * 16 + ((lane >> 4) << 3) + l7;
        rowB[bp] = row * 64;  swB[bp] = swzs(row);
    }
    const int cselB = (lane >> 3) & 1;

    float acc[2][4][4];
    #pragma unroll
    for (int i = 0; i < 2; i++)
        #pragma unroll
        for (int j = 0; j < 4; j++)
            #pragma unroll
            for (int q = 0; q < 4; q++) acc[i][j][q] = 0.f;

    const int T = Kd >> 5;   // BK = 32

    #pragma unroll
    for (int s = 0; s < 3; ++s) {
        const int k0 = s << 5;
        const uint32_t sa = sbase + s * 12288, sb = sa + 4096;
        cp16(sa + da, gA + k0);
        cp16(sb + d0, gB0 + k0);  cp16(sb + d1, gB1 + k0);
        CP_COMMIT();
    }
    // resid tile prefetch: 64 rows x 128 fp32 (cols [bn, bn+128)) = 2048
    // 16B chunks, 8/thread, padded rows. Own commit group (4th); retired by
    // the t=2 ring wait, i.e. long before the epilogue needs it.
    {
        #pragma unroll
        for (int i = 0; i < 8; ++i) {
            const int cid = tid + 256 * i;          // 0..2047
            const int row = cid >> 5;               // 0..63
            const int cc  = cid & 31;               // 16B chunk in row
            cp16(sresid + row * (PROJ_RESID_STRIDE * 4) + cc * 16,
                 resid + (size_t)(bm + row) * N + bn + cc * 4);
        }
        CP_COMMIT();
    }

    for (int t = 0; t < T; ++t) {
        if (t + 3 <= T) CP_WAIT2();
        else if (t + 2 == T) CP_WAIT1();
        else CP_WAIT0();
        __syncthreads();

        if (t + 3 < T) {
            const int s2 = (t + 3) & 3;
            const int k0 = (t + 3) << 5;
            const uint32_t sa = sbase + s2 * 12288, sb = sa + 4096;
            cp16(sa + da, gA + k0);
            cp16(sb + d0, gB0 + k0);  cp16(sb + d1, gB1 + k0);
            CP_COMMIT();
        }

        const uint32_t sa = sbase + (t & 3) * 12288, sb = sa + 4096;
        #pragma unroll
        for (int g = 0; g < 2; ++g) {
            uint32_t af[2][4], bf[2][4];
            #pragma unroll
            for (int am = 0; am < 2; am++)
                ldsm4(af[am], sa + rowA[am] + ((((g << 1) | cselA) ^ swA[am]) << 4));
            #pragma unroll
            for (int bp = 0; bp < 2; bp++)
                ldsm4(bf[bp], sb + rowB[bp] + ((((g << 1) | cselB) ^ swB[bp]) << 4));
            #pragma unroll
            for (int am = 0; am < 2; am++)
                #pragma unroll
                for (int nb = 0; nb < 4; nb++)
                    mma_bf16(acc[am][nb], af[am], &bf[nb >> 1][(nb & 1) << 1]);
        }
    }

    // ---- epilogue: bias + resid (from smem), fp32 out ----
    const float* rs = (const float*)(smem + PROJ_RING_BYTES);
    const int r4 = lane >> 2, c4 = lane & 3;
    #pragma unroll
    for (int am = 0; am < 2; ++am) {
        const int lr = wm * 32 + am * 16 + r4;       // local row in [0,64)
        const int m0 = bm + lr;
        #pragma unroll
        for (int nb = 0; nb < 4; ++nb) {
            const int lc = wn * 32 + nb * 8 + c4 * 2;   // local col in [0,128)
            const int n0 = bn + lc;
            float2 v01 = make_float2(acc[am][nb][0], acc[am][nb][1]);
            float2 v23 = make_float2(acc[am][nb][2], acc[am][nb][3]);
            const float2 bz = *(const float2*)(bias + n0);
            const float2 q0 = *(const float2*)(rs + lr * PROJ_RESID_STRIDE + lc);
            const float2 q1 = *(const float2*)(rs + (lr + 8) * PROJ_RESID_STRIDE + lc);
            v01.x += bz.x + q0.x;  v01.y += bz.y + q0.y;
            v23.x += bz.x + q1.x;  v23.y += bz.y + q1.y;
            *(float2*)(C + (size_t)m0 * N + n0)       = v01;
            *(float2*)(C + (size_t)(m0 + 8) * N + n0) = v23;
        }
    }
}

// ===========================================================================
// prep kernel: blocks 0..1 build the per-batch spatial grid; remaining
// blocks convert fp32 -> bf16 via three branch-free grid-stride loops.
// ===========================================================================
__global__ void __launch_bounds__(1024) prep_kernel(
    const float* __restrict__ x, const float* __restrict__ coords,
    const float* __restrict__ w_qkv, const float* __restrict__ w_proj)
{
    if (blockIdx.x < BATCH) {
        const int b = blockIdx.x;
        __shared__ int cnt[CELLS];
        __shared__ int part[1024];
        const int t = threadIdx.x;
        #pragma unroll
        for (int i = t; i < CELLS; i += 1024) cnt[i] = 0;
        __syncthreads();

        const float2* cb = (const float2*)coords + (size_t)b * NTOK;
        int pcid[4]; float2 pc[4];
        #pragma unroll
        for (int j = 0; j < 4; j++) {
            const int p = t + j * 1024;
            const float2 c = cb[p];
            const int cx = min(GRID - 1, max(0, (int)(c.x * INVCELL)));
            const int cy = min(GRID - 1, max(0, (int)(c.y * INVCELL)));
            pcid[j] = cy * GRID + cx;  pc[j] = c;
            atomicAdd(&cnt[pcid[j]], 1);
        }
        __syncthreads();

        const int c0 = cnt[t*4], c1 = cnt[t*4+1], c2 = cnt[t*4+2], c3 = cnt[t*4+3];
        const int lsum = c0 + c1 + c2 + c3;
        part[t] = lsum;
        __syncthreads();
        for (int off = 1; off < 1024; off <<= 1) {
            const int v = (t >= off) ? part[t - off] : 0;
            __syncthreads();
            part[t] += v;
            __syncthreads();
        }
        const int excl = part[t] - lsum;
        const int s0 = excl, s1 = excl + c0, s2 = s1 + c1, s3 = s2 + c2;
        cnt[t*4] = s0; cnt[t*4+1] = s1; cnt[t*4+2] = s2; cnt[t*4+3] = s3;
        int* csg = g_cellstart + b * (CELLS + 1);
        csg[t*4] = s0; csg[t*4+1] = s1; csg[t*4+2] = s2; csg[t*4+3] = s3;
        if (t == 1023) csg[CELLS] = NTOK;
        __syncthreads();

        #pragma unroll
        for (int j = 0; j < 4; j++) {
            const int pos = atomicAdd(&cnt[pcid[j]], 1);
            g_scoord[b * NTOK + pos] = pc[j];
            g_sidx[b * NTOK + pos]   = t + j * 1024;
        }
    } else {
        const long stride = (long)(gridDim.x - BATCH) * 1024;
        const long base   = (long)(blockIdx.x - BATCH) * 1024 + threadIdx.x;

        constexpr long X8 = (long)MROWS * DMODEL / 8;        // 524288
        const float4* xs = (const float4*)x;
        uint4* xd = (uint4*)g_xb;
        for (long i = base; i < X8; i += stride) xd[i] = cvt2f4(xs, i);

        constexpr long W8 = (long)3 * DMODEL * DMODEL / 8;   // 98304
        const float4* ws = (const float4*)w_qkv;
        uint4* wd = (uint4*)g_wqb;
        for (long i = base; i < W8; i += stride) wd[i] = cvt2f4(ws, i);

        constexpr long P8 = (long)DMODEL * DMODEL / 8;       // 32768
        const float4* ps = (const float4*)w_proj;
        uint4* pd = (uint4*)g_wpb;
        for (long i = base; i < P8; i += stride) pd[i] = cvt2f4(ps, i);
    }
}

// ===========================================================================
// grid kNN query: one thread per query; exact top-9 via ring expansion with
// cell-box lower-bound pruning (proven fastest config).
// ===========================================================================
__device__ __forceinline__ void scan_cell(
    int X, int Y, float qx, float qy,
    const int* __restrict__ cs, const float2* __restrict__ sc,
    const int* __restrict__ si,
    float (&d9)[KNN], int (&i9)[KNN], float& dmax, int& imax)
{
    const float lx = X * CELLSZ, ly = Y * CELLSZ;
    const float ddx = fmaxf(0.f, fmaxf(lx - qx, qx - (lx + CELLSZ)));
    const float ddy = fmaxf(0.f, fmaxf(ly - qy, qy - (ly + CELLSZ)));
    if (ddx * ddx + ddy * ddy >= dmax) return;
    const int cid = Y * GRID + X;
    const int s1 = cs[cid + 1];
    for (int s = cs[cid]; s < s1; ++s) {
        const float2 p = sc[s];
        const float dx = p.x - qx, dy = p.y - qy;
        const float d2 = dx * dx + dy * dy;
        if (d2 < dmax) {
            const int idx = si[s];
            #pragma unroll
            for (int j = 0; j < KNN; j++)
                if (j == imax) { d9[j] = d2; i9[j] = idx; }
            dmax = d9[0]; imax = 0;
            #pragma unroll
            for (int j = 1; j < KNN; j++)
                if (d9[j] > dmax) { dmax = d9[j]; imax = j; }
        }
    }
}

__device__ __forceinline__ void knn_query(const float* __restrict__ coords, int q)
{
    const int b = q >> 12, n = q & (NTOK - 1);
    const float2 qc = ((const float2*)coords)[(size_t)b * NTOK + n];
    const float qx = qc.x, qy = qc.y;
    const int cx = min(GRID - 1, max(0, (int)(qx * INVCELL)));
    const int cy = min(GRID - 1, max(0, (int)(qy * INVCELL)));
    const int*    cs = g_cellstart + b * (CELLS + 1);
    const float2* sc = g_scoord + b * NTOK;
    const int*    si = g_sidx + b * NTOK;

    float d9[KNN]; int i9[KNN];
    #pragma unroll
    for (int j = 0; j < KNN; j++) { d9[j] = 3.4e38f; i9[j] = 0; }
    float dmax = 3.4e38f; int imax = 0;

    for (int r = 0; r < GRID; ++r) {
        const int xlo = max(cx - r, 0), xhi = min(cx + r, GRID - 1);
        if (r == 0) {
            scan_cell(cx, cy, qx, qy, cs, sc, si, d9, i9, dmax, imax);
        } else {
            if (cy - r >= 0)
                for (int X = xlo; X <= xhi; X++)
                    scan_cell(X, cy - r, qx, qy, cs, sc, si, d9, i9, dmax, imax);
            if (cy + r <= GRID - 1)
                for (int X = xlo; X <= xhi; X++)
                    scan_cell(X, cy + r, qx, qy, cs, sc, si, d9, i9, dmax, imax);
            const int yl = max(cy - r + 1, 0), yh = min(cy + r - 1, GRID - 1);
            if (cx - r >= 0)
                for (int Y = yl; Y <= yh; Y++)
                    scan_cell(cx - r, Y, qx, qy, cs, sc, si, d9, i9, dmax, imax);
            if (cx + r <= GRID - 1)
                for (int Y = yl; Y <= yh; Y++)
                    scan_cell(cx + r, Y, qx, qy, cs, sc, si, d9, i9, dmax, imax);
        }
        const float rs = r * CELLSZ;
        if (rs * rs >= dmax) break;
    }
    #pragma unroll
    for (int j = 0; j < KNN; j++) g_nn[(size_t)q * KNN + j] = i9[j];
}

// ===========================================================================
// Fused launch: blocks [0,32) = kNN (thread-per-query, FIRST so it hides
// under the GEMM waves); blocks [32, 800) = QKV GEMM tiles (128x128).
// ===========================================================================
#define KNN_BLOCKS 32

__global__ void __launch_bounds__(256, 2) qkv_knn_kernel(const float* __restrict__ coords)
{
    extern __shared__ __align__(128) unsigned char smem[];
    if (blockIdx.x < KNN_BLOCKS) {
        knn_query(coords, blockIdx.x * 256 + threadIdx.x);
    } else {
        const int idx = blockIdx.x - KNN_BLOCKS;
        gemm_body128(g_xb, g_wqb, 3 * DMODEL, DMODEL,
                     (idx / 12) * 128, (idx % 12) * 128, smem);
    }
}

__global__ void __launch_bounds__(256, 2) proj_kernel(
    float* __restrict__ C, const float* __restrict__ bias, const float* __restrict__ resid)
{
    extern __shared__ __align__(128) unsigned char smem[];
    gemm_body64(g_attnb, g_wpb, C, DMODEL, DMODEL, bias, resid,
                blockIdx.y * 64, blockIdx.x * 128, smem);
}

// ---------------------------------------------------------------------------
// Attention: one WARP per token, full-row vectorized (proven config).
// Lane l owns dims [16l, 16l+16); head logit via 2-shfl reduce in 4-lane group.
// Fused exact-erf GELU; bf16 out. No smem, no block sync.
// ---------------------------------------------------------------------------
__device__ __forceinline__ float dot8_bf16(uint4 a, uint4 b) {
    const uint32_t* pa = (const uint32_t*)&a;
    const uint32_t* pb = (const uint32_t*)&b;
    float s = 0.f;
    #pragma unroll
    for (int i = 0; i < 4; i++) {
        const float2 fa = __bfloat1622float2(*(const __nv_bfloat162*)&pa[i]);
        const float2 fb = __bfloat1622float2(*(const __nv_bfloat162*)&pb[i]);
        s = fmaf(fa.x, fb.x, s);
        s = fmaf(fa.y, fb.y, s);
    }
    return s;
}
__device__ __forceinline__ void fma8_bf16(float* acc, float w, uint4 v) {
    const uint32_t* pv = (const uint32_t*)&v;
    #pragma unroll
    for (int i = 0; i < 4; i++) {
        const float2 fv = __bfloat1622float2(*(const __nv_bfloat162*)&pv[i]);
        acc[2*i]   = fmaf(w, fv.x, acc[2*i]);
        acc[2*i+1] = fmaf(w, fv.y, acc[2*i+1]);
    }
}

__global__ void __launch_bounds__(256) attn_kernel()
{
    const int r    = blockIdx.x * 8 + (threadIdx.x >> 5);   // token 0..8191
    const int lane = threadIdx.x & 31;
    const int b    = r >> 12;

    int idxv = 0;
    if (lane < KNN) idxv = (b << 12) + g_nn[(size_t)r * KNN + lane];
    int idx[KNN];
    #pragma unroll
    for (int j = 0; j < KNN; j++) idx[j] = __shfl_sync(0xffffffffu, idxv, j);

    const uint4* qrow = (const uint4*)(g_qb + (size_t)r * DMODEL) + lane * 2;
    const uint4 q0 = qrow[0], q1 = qrow[1];

    float logit[KNN];
    #pragma unroll
    for (int j = 0; j < KNN; j++) {
        const uint4* krow = (const uint4*)(g_kvb + (size_t)idx[j] * (2 * DMODEL)) + lane * 2;
        const uint4 k0 = krow[0], k1 = krow[1];
        float p = dot8_bf16(q0, k0) + dot8_bf16(q1, k1);
        p += __shfl_xor_sync(0xffffffffu, p, 1);
        p += __shfl_xor_sync(0xffffffffu, p, 2);
        logit[j] = p * 0.125f;
    }

    float mx = logit[0];
    #pragma unroll
    for (int j = 1; j < KNN; j++) mx = fmaxf(mx, logit[j]);
    float sum = 0.f;
    #pragma unroll
    for (int j = 0; j < KNN; j++) { logit[j] = __expf(logit[j] - mx); sum += logit[j]; }
    const float inv = 1.f / sum;

    float acc[16];
    #pragma unroll
    for (int i = 0; i < 16; i++) acc[i] = 0.f;
    #pragma unroll
    for (int j = 0; j < KNN; j++) {
        const uint4* vrow = (const uint4*)(g_kvb + (size_t)idx[j] * (2 * DMODEL) + DMODEL)
                            + lane * 2;
        const uint4 v0 = vrow[0], v1 = vrow[1];
        const float w = logit[j] * inv;
        fma8_bf16(acc,     w, v0);
        fma8_bf16(acc + 8, w, v1);
    }

    uint4 o[2];
    uint32_t* po = (uint32_t*)o;
    #pragma unroll
    for (int i = 0; i < 8; i++) {
        float a = acc[2*i],   bq = acc[2*i+1];
        a  = 0.5f * a  * (1.f + erff(a  * 0.70710678118654752f));
        bq = 0.5f * bq * (1.f + erff(bq * 0.70710678118654752f));
        const __nv_bfloat162 pk = __floats2bfloat162_rn(a, bq);
        po[i] = *(const uint32_t*)&pk;
    }
    uint4* orow = (uint4*)(g_attnb + (size_t)r * DMODEL) + lane * 2;
    orow[0] = o[0];
    orow[1] = o[1];
}

// ---------------------------------------------------------------------------
// kernel_launch: x, coords, w_qkv, w_proj, b_proj  ->  out (fp32, B*N*D)
// ---------------------------------------------------------------------------
extern "C" void kernel_launch(void* const* d_in, const int* in_sizes, int n_in,
                              void* d_out, int out_size)
{
    const float* x      = (const float*)d_in[0];
    const float* coords = (const float*)d_in[1];
    const float* w_qkv  = (const float*)d_in[2];
    const float* w_proj = (const float*)d_in[3];
    const float* b_proj = (const float*)d_in[4];
    float* out = (float*)d_out;

    constexpr int SMEM_QKV  = 65536;            // 4 x 16KB
    constexpr int SMEM_PROJ = PROJ_SMEM_TOTAL;  // 48KB ring + 33KB resid
    cudaFuncSetAttribute(qkv_knn_kernel, cudaFuncAttributeMaxDynamicSharedMemorySize, SMEM_QKV);
    cudaFuncSetAttribute(proj_kernel,    cudaFuncAttributeMaxDynamicSharedMemorySize, SMEM_PROJ);

    // 1) grid build (2 blocks) + fp32->bf16 conversion (one wave: 294 blocks)
    prep_kernel<<<BATCH + 294, 1024>>>(x, coords, w_qkv, w_proj);

    // 2) kNN (32 blocks, first) + QKV GEMM (768 blocks of 128x128)
    qkv_knn_kernel<<<KNN_BLOCKS + 768, 256, SMEM_QKV>>>(coords);

    // 3) neighbor attention + GELU (warp-per-token, bf16 out)
    attn_kernel<<<MROWS / 8, 256>>>();

    // 4) output projection + bias + residual (512 CTAs of 64x128)
    {
        dim3 grid(DMODEL / 128, MROWS / 64);
        proj_kernel<<<grid, 256, SMEM_PROJ>>>(out, b_proj, x);
    }
}